// round 1
// baseline (speedup 1.0000x reference)
#include <cuda_runtime.h>

#define Bn 256
#define Qn 16
#define Sn 512
#define Mn 8
#define Dn 128
#define NT 256
#define TILE 64
#define NTILES (Sn/TILE)
#define PPITCH 520

// shared memory layout (float offsets)
#define OFF_QT   0                        // qT[128][16]
#define OFF_P    (OFF_QT + Dn*16)         // p[16][520]
#define OFF_W    (OFF_P + Qn*PPITCH)      // w[512]
#define OFF_KTS  (OFF_W + Sn)             // score K tile [64][129]
#define OFF_KT   (OFF_KTS + TILE*129)     // main K tile [64][128]
#define OFF_VT   (OFF_KT + TILE*Dn)       // main V tile [64][128]
#define OFF_OUT  (OFF_VT + TILE*Dn)       // out[16][128]
#define OFF_KBAR (OFF_OUT + Qn*Dn)        // kbar[16][128]
#define OFF_KCG  (OFF_KBAR + Qn*Dn)       // kcg[8][129]
#define OFF_VCG  (OFF_KCG + Mn*129)       // vcg[8][129]
#define OFF_PCG  (OFF_VCG + Mn*129)       // p_cg[16][8]
#define OFF_WCG  (OFF_PCG + Qn*Mn)        // w_cg[8]
#define OFF_OCG  (OFF_WCG + Mn)           // out_cg[16][128]
#define OFF_KBCG (OFF_OCG + Qn*Dn)        // kbar_cg[16][128]
#define OFF_RED  (OFF_KBCG + Qn*Dn)       // 8 warps * 4
#define SMEM_FLOATS (OFF_RED + 32)

__device__ float g_losses[Bn];

__device__ __forceinline__ float clip50(float x) {
    return fminf(fmaxf(x, -50.0f), 50.0f);
}

__global__ void __launch_bounds__(NT, 1)
fml_kernel(const float* __restrict__ gq, const float* __restrict__ gk,
           const float* __restrict__ gv, const float* __restrict__ gkcg,
           const float* __restrict__ gvcg)
{
    extern __shared__ float sm[];
    const int b   = blockIdx.x;
    const int tid = threadIdx.x;
    const float scale = 0.088388347648318447f;   // 128^-0.5

    // ---- load qT (transposed, [d][q]) and cg tensors (pad 129) ----
    const float* qb = gq + (size_t)b * Qn * Dn;
    for (int i = tid; i < Qn*Dn; i += NT) {
        int qq = i >> 7, d = i & 127;
        sm[OFF_QT + d*16 + qq] = qb[i];
    }
    const float* kcb = gkcg + (size_t)b * Mn * Dn;
    const float* vcb = gvcg + (size_t)b * Mn * Dn;
    for (int i = tid; i < Mn*Dn; i += NT) {
        int j = i >> 7, d = i & 127;
        sm[OFF_KCG + j*129 + d] = kcb[i];
        sm[OFF_VCG + j*129 + d] = vcb[i];
    }
    __syncthreads();

    // ---- cg scores (16x8) ----
    if (tid < Qn*Mn) {
        int qq = tid >> 3, j = tid & 7;
        float acc = 0.f;
        #pragma unroll 8
        for (int d = 0; d < Dn; ++d)
            acc = fmaf(sm[OFF_QT + d*16 + qq], sm[OFF_KCG + j*129 + d], acc);
        sm[OFF_PCG + qq*Mn + j] = acc * scale;
    }
    __syncthreads();
    // ---- cg softmax (rows of 8) ----
    if (tid < Qn) {
        float m = -1e30f;
        #pragma unroll
        for (int j = 0; j < Mn; ++j) m = fmaxf(m, sm[OFF_PCG + tid*Mn + j]);
        float ss = 0.f;
        #pragma unroll
        for (int j = 0; j < Mn; ++j) {
            float e = __expf(sm[OFF_PCG + tid*Mn + j] - m);
            sm[OFF_PCG + tid*Mn + j] = e; ss += e;
        }
        float inv = 1.f / ss;
        #pragma unroll
        for (int j = 0; j < Mn; ++j) sm[OFF_PCG + tid*Mn + j] *= inv;
    }
    __syncthreads();
    if (tid < Mn) {
        float a = 0.f;
        #pragma unroll
        for (int qq = 0; qq < Qn; ++qq) a += sm[OFF_PCG + qq*Mn + tid];
        sm[OFF_WCG + tid] = a;
    }
    // ---- cg out / kbar ----
    {
        int qq = tid >> 4, dblk = tid & 15;
        float o[8], kb[8];
        #pragma unroll
        for (int i = 0; i < 8; ++i) { o[i] = 0.f; kb[i] = 0.f; }
        #pragma unroll
        for (int j = 0; j < Mn; ++j) {
            float pc = sm[OFF_PCG + qq*Mn + j];
            #pragma unroll
            for (int i = 0; i < 8; ++i) {
                o[i]  = fmaf(pc, sm[OFF_VCG + j*129 + dblk*8 + i], o[i]);
                kb[i] = fmaf(pc, sm[OFF_KCG + j*129 + dblk*8 + i], kb[i]);
            }
        }
        #pragma unroll
        for (int i = 0; i < 8; ++i) {
            sm[OFF_OCG  + qq*Dn + dblk*8 + i] = o[i];
            sm[OFF_KBCG + qq*Dn + dblk*8 + i] = kb[i];
        }
    }

    // ---- dense scores: p[q][s] = scale * q·k_s ----
    const float* kbase = gk + (size_t)b * Sn * Dn;
    const float* vbase = gv + (size_t)b * Sn * Dn;
    const int qg = tid >> 6;        // 4 groups of 4 queries
    const int sl = tid & 63;        // s within tile
    for (int t = 0; t < NTILES; ++t) {
        __syncthreads();
        const float4* kg4 = (const float4*)(kbase + (size_t)t * TILE * Dn);
        #pragma unroll
        for (int it = 0; it < 8; ++it) {
            int fidx = tid + it*NT;               // [0,2048)
            int row = fidx >> 5, c4 = fidx & 31;
            float4 val = kg4[fidx];
            float* dst = &sm[OFF_KTS + row*129 + c4*4];
            dst[0]=val.x; dst[1]=val.y; dst[2]=val.z; dst[3]=val.w;
        }
        __syncthreads();
        float a0=0.f, a1=0.f, a2=0.f, a3=0.f;
        #pragma unroll 8
        for (int d = 0; d < Dn; ++d) {
            float kv = sm[OFF_KTS + sl*129 + d];
            float4 q4 = *(const float4*)&sm[OFF_QT + d*16 + qg*4];
            a0 = fmaf(q4.x, kv, a0); a1 = fmaf(q4.y, kv, a1);
            a2 = fmaf(q4.z, kv, a2); a3 = fmaf(q4.w, kv, a3);
        }
        int scol = t*TILE + sl;
        sm[OFF_P + (qg*4+0)*PPITCH + scol] = a0*scale;
        sm[OFF_P + (qg*4+1)*PPITCH + scol] = a1*scale;
        sm[OFF_P + (qg*4+2)*PPITCH + scol] = a2*scale;
        sm[OFF_P + (qg*4+3)*PPITCH + scol] = a3*scale;
    }
    __syncthreads();

    // ---- softmax rows (warp handles rows wid and wid+8) ----
    const int wid = tid >> 5, lane = tid & 31;
    #pragma unroll
    for (int r = 0; r < 2; ++r) {
        int qq = wid + r*8;
        float* row = &sm[OFF_P + qq*PPITCH];
        float m = -1e30f;
        #pragma unroll
        for (int i = 0; i < 16; ++i) m = fmaxf(m, row[lane + 32*i]);
        #pragma unroll
        for (int o = 16; o > 0; o >>= 1) m = fmaxf(m, __shfl_xor_sync(0xffffffffu, m, o));
        float ss = 0.f;
        float ev[16];
        #pragma unroll
        for (int i = 0; i < 16; ++i) { ev[i] = __expf(row[lane+32*i] - m); ss += ev[i]; }
        #pragma unroll
        for (int o = 16; o > 0; o >>= 1) ss += __shfl_xor_sync(0xffffffffu, ss, o);
        float inv = 1.f / ss;
        #pragma unroll
        for (int i = 0; i < 16; ++i) row[lane+32*i] = ev[i]*inv;
    }
    __syncthreads();
    // ---- w[s] = column sums ----
    for (int s = tid; s < Sn; s += NT) {
        float a = 0.f;
        #pragma unroll
        for (int qq = 0; qq < Qn; ++qq) a += sm[OFF_P + qq*PPITCH + s];
        sm[OFF_W + s] = a;
    }

    // ---- fused main pass: J1 += w_j * v_j k_j^T ; out += pV ; kbar += pK ----
    const int ty = tid >> 4, tx = tid & 15;   // J tile: rows ty*8.., cols tx*8..
    float acc[8][8];
    #pragma unroll
    for (int i = 0; i < 8; ++i)
        #pragma unroll
        for (int e = 0; e < 8; ++e) acc[i][e] = 0.f;
    float ao[4][2], ak[4][2];
    #pragma unroll
    for (int i2 = 0; i2 < 4; ++i2) { ao[i2][0]=ao[i2][1]=ak[i2][0]=ak[i2][1]=0.f; }

    for (int t = 0; t < NTILES; ++t) {
        __syncthreads();
        const float4* kg4 = (const float4*)(kbase + (size_t)t * TILE * Dn);
        const float4* vg4 = (const float4*)(vbase + (size_t)t * TILE * Dn);
        #pragma unroll
        for (int it = 0; it < 8; ++it) {
            int fidx = tid + it*NT;
            ((float4*)&sm[OFF_KT])[fidx] = kg4[fidx];
            ((float4*)&sm[OFF_VT])[fidx] = vg4[fidx];
        }
        __syncthreads();
        #pragma unroll 2
        for (int j = 0; j < TILE; ++j) {
            float wj = sm[OFF_W + t*TILE + j];
            float4 va  = *(const float4*)&sm[OFF_VT + j*Dn + ty*8];
            float4 vb2 = *(const float4*)&sm[OFF_VT + j*Dn + ty*8 + 4];
            float4 ka  = *(const float4*)&sm[OFF_KT + j*Dn + tx*8];
            float4 kb2 = *(const float4*)&sm[OFF_KT + j*Dn + tx*8 + 4];
            float vr[8] = {va.x*wj, va.y*wj, va.z*wj, va.w*wj,
                           vb2.x*wj, vb2.y*wj, vb2.z*wj, vb2.w*wj};
            float kr[8] = {ka.x, ka.y, ka.z, ka.w, kb2.x, kb2.y, kb2.z, kb2.w};
            #pragma unroll
            for (int i = 0; i < 8; ++i)
                #pragma unroll
                for (int e = 0; e < 8; ++e)
                    acc[i][e] = fmaf(vr[i], kr[e], acc[i][e]);
            // out / kbar (mapping: q-group qg, d-pair sl)
            float2 vv = *(const float2*)&sm[OFF_VT + j*Dn + sl*2];
            float2 kk = *(const float2*)&sm[OFF_KT + j*Dn + sl*2];
            #pragma unroll
            for (int i2 = 0; i2 < 4; ++i2) {
                float pc = sm[OFF_P + (qg*4+i2)*PPITCH + t*TILE + j];
                ao[i2][0] = fmaf(pc, vv.x, ao[i2][0]);
                ao[i2][1] = fmaf(pc, vv.y, ao[i2][1]);
                ak[i2][0] = fmaf(pc, kk.x, ak[i2][0]);
                ak[i2][1] = fmaf(pc, kk.y, ak[i2][1]);
            }
        }
    }
    // store out/kbar to smem
    #pragma unroll
    for (int i2 = 0; i2 < 4; ++i2) {
        sm[OFF_OUT  + (qg*4+i2)*Dn + sl*2 + 0] = ao[i2][0];
        sm[OFF_OUT  + (qg*4+i2)*Dn + sl*2 + 1] = ao[i2][1];
        sm[OFF_KBAR + (qg*4+i2)*Dn + sl*2 + 0] = ak[i2][0];
        sm[OFF_KBAR + (qg*4+i2)*Dn + sl*2 + 1] = ak[i2][1];
    }
    __syncthreads();

    // ---- dense J2: acc -= out_q (x) kbar_q ----
    #pragma unroll
    for (int qq = 0; qq < Qn; ++qq) {
        float4 oa = *(const float4*)&sm[OFF_OUT  + qq*Dn + ty*8];
        float4 ob = *(const float4*)&sm[OFF_OUT  + qq*Dn + ty*8 + 4];
        float4 k1 = *(const float4*)&sm[OFF_KBAR + qq*Dn + tx*8];
        float4 k2 = *(const float4*)&sm[OFF_KBAR + qq*Dn + tx*8 + 4];
        float ov[8] = {oa.x,oa.y,oa.z,oa.w, ob.x,ob.y,ob.z,ob.w};
        float kv[8] = {k1.x,k1.y,k1.z,k1.w, k2.x,k2.y,k2.z,k2.w};
        #pragma unroll
        for (int i = 0; i < 8; ++i)
            #pragma unroll
            for (int e = 0; e < 8; ++e)
                acc[i][e] = fmaf(-ov[i], kv[e], acc[i][e]);
    }

    // ---- cg jacobian (same thread tile) ----
    float jc[8][8];
    #pragma unroll
    for (int i = 0; i < 8; ++i)
        #pragma unroll
        for (int e = 0; e < 8; ++e) jc[i][e] = 0.f;
    #pragma unroll
    for (int j = 0; j < Mn; ++j) {
        float wj = sm[OFF_WCG + j];
        float vr[8], kr[8];
        #pragma unroll
        for (int i = 0; i < 8; ++i) {
            vr[i] = wj * sm[OFF_VCG + j*129 + ty*8 + i];
            kr[i] = sm[OFF_KCG + j*129 + tx*8 + i];
        }
        #pragma unroll
        for (int i = 0; i < 8; ++i)
            #pragma unroll
            for (int e = 0; e < 8; ++e)
                jc[i][e] = fmaf(vr[i], kr[e], jc[i][e]);
    }
    #pragma unroll
    for (int qq = 0; qq < Qn; ++qq) {
        float ov[8], kv[8];
        #pragma unroll
        for (int i = 0; i < 8; ++i) {
            ov[i] = sm[OFF_OCG  + qq*Dn + ty*8 + i];
            kv[i] = sm[OFF_KBCG + qq*Dn + tx*8 + i];
        }
        #pragma unroll
        for (int i = 0; i < 8; ++i)
            #pragma unroll
            for (int e = 0; e < 8; ++e)
                jc[i][e] = fmaf(-ov[i], kv[e], jc[i][e]);
    }

    // ---- clip + cosine partials + consistency ----
    float dd = 0.f, cc = 0.f, dc = 0.f;
    #pragma unroll
    for (int i = 0; i < 8; ++i)
        #pragma unroll
        for (int e = 0; e < 8; ++e) {
            float jd_ = clip50(acc[i][e] * scale);
            float jcv = clip50(jc[i][e] * scale);
            dd = fmaf(jd_, jd_, dd);
            cc = fmaf(jcv, jcv, cc);
            dc = fmaf(jd_, jcv, dc);
        }
    float cons = 0.f;
    #pragma unroll
    for (int i = 0; i < 8; ++i) {
        float dif = sm[OFF_OUT + tid*8 + i] - sm[OFF_OCG + tid*8 + i];
        cons = fmaf(dif, dif, cons);
    }

    // ---- block reduce ----
    #pragma unroll
    for (int o = 16; o > 0; o >>= 1) {
        dd   += __shfl_xor_sync(0xffffffffu, dd,   o);
        cc   += __shfl_xor_sync(0xffffffffu, cc,   o);
        dc   += __shfl_xor_sync(0xffffffffu, dc,   o);
        cons += __shfl_xor_sync(0xffffffffu, cons, o);
    }
    if (lane == 0) {
        sm[OFF_RED + wid*4 + 0] = dd;
        sm[OFF_RED + wid*4 + 1] = cc;
        sm[OFF_RED + wid*4 + 2] = dc;
        sm[OFF_RED + wid*4 + 3] = cons;
    }
    __syncthreads();
    if (tid == 0) {
        float DD=0.f, CC=0.f, DC=0.f, CO=0.f;
        #pragma unroll
        for (int w8 = 0; w8 < 8; ++w8) {
            DD += sm[OFF_RED + w8*4 + 0];
            CC += sm[OFF_RED + w8*4 + 1];
            DC += sm[OFF_RED + w8*4 + 2];
            CO += sm[OFF_RED + w8*4 + 3];
        }
        float cosv = DC / (sqrtf(DD) * sqrtf(CC) + 1e-8f);
        g_losses[b] = (1.0f - cosv) + CO * (1.0f / (float)(Qn * Dn));
    }
}

__global__ void fml_reduce(float* out) {
    __shared__ float s[Bn];
    s[threadIdx.x] = g_losses[threadIdx.x];
    __syncthreads();
    if (threadIdx.x == 0) {
        float a = 0.f;
        for (int i = 0; i < Bn; ++i) a += s[i];   // fixed order -> deterministic
        out[0] = a * (1.0f / (float)Bn);
    }
}

extern "C" void kernel_launch(void* const* d_in, const int* in_sizes, int n_in,
                              void* d_out, int out_size)
{
    const float* q   = (const float*)d_in[0];
    const float* k   = (const float*)d_in[1];
    const float* v   = (const float*)d_in[2];
    const float* kcg = (const float*)d_in[3];
    const float* vcg = (const float*)d_in[4];

    cudaFuncSetAttribute(fml_kernel, cudaFuncAttributeMaxDynamicSharedMemorySize,
                         SMEM_FLOATS * (int)sizeof(float));
    fml_kernel<<<Bn, NT, SMEM_FLOATS * sizeof(float)>>>(q, k, v, kcg, vcg);
    fml_reduce<<<1, Bn>>>((float*)d_out);
}

// round 2
// speedup vs baseline: 1.0635x; 1.0635x over previous
#include <cuda_runtime.h>

#define Bn 256
#define Qn 16
#define Sn 512
#define Mn 8
#define Dn 128
#define NT 256
#define TILE 64
#define NTILES (Sn/TILE)
#define PPITCH 520
#define CGP 132

typedef unsigned long long ull;

// shared memory layout (float offsets)
#define OFF_QT   0                        // qT[128][16]
#define OFF_P    (OFF_QT + Dn*16)         // p[16][520]
#define OFF_W    (OFF_P + Qn*PPITCH)      // w[512]
#define OFF_KTS  (OFF_W + Sn)             // score K tile [64][129]
#define OFF_KT   (OFF_KTS + TILE*129)     // main K tile [64][128]
#define OFF_VT   (OFF_KT + TILE*Dn)       // main V tile [64][128]
#define OFF_OUT  (OFF_VT + TILE*Dn)       // out[16][128]
#define OFF_KBAR (OFF_OUT + Qn*Dn)        // kbar[16][128]
#define OFF_KCG  (OFF_KBAR + Qn*Dn)       // kcg[8][132]
#define OFF_VCG  (OFF_KCG + Mn*CGP)       // vcg[8][132]
#define OFF_PCG  (OFF_VCG + Mn*CGP)       // p_cg[16][8]
#define OFF_WCG  (OFF_PCG + Qn*Mn)        // w_cg[8]
#define OFF_OCG  (OFF_WCG + Mn)           // out_cg[16][128]
#define OFF_KBCG (OFF_OCG + Qn*Dn)        // kbar_cg[16][128]
#define OFF_RED  (OFF_KBCG + Qn*Dn)       // 8 warps * 4
#define SMEM_FLOATS (OFF_RED + 32)

__device__ float g_losses[Bn];

__device__ __forceinline__ float clip50(float x) {
    return fminf(fmaxf(x, -50.0f), 50.0f);
}
__device__ __forceinline__ ull dup2(float x) {
    ull r; asm("mov.b64 %0, {%1, %1};" : "=l"(r) : "f"(x)); return r;
}
__device__ __forceinline__ ull fma2(ull a, ull b, ull c) {
    ull d; asm("fma.rn.f32x2 %0, %1, %2, %3;" : "=l"(d) : "l"(a), "l"(b), "l"(c)); return d;
}
__device__ __forceinline__ float2 unpack2(ull p) {
    float2 f; asm("mov.b64 {%0, %1}, %2;" : "=f"(f.x), "=f"(f.y) : "l"(p)); return f;
}

__global__ void __launch_bounds__(NT, 1)
fml_kernel(const float* __restrict__ gq, const float* __restrict__ gk,
           const float* __restrict__ gv, const float* __restrict__ gkcg,
           const float* __restrict__ gvcg)
{
    extern __shared__ float sm[];
    const int b   = blockIdx.x;
    const int tid = threadIdx.x;
    const float scale = 0.088388347648318447f;   // 128^-0.5

    // ---- load qT (transposed, [d][q]) and cg tensors (pad 132) ----
    const float* qb = gq + (size_t)b * Qn * Dn;
    for (int i = tid; i < Qn*Dn; i += NT) {
        int qq = i >> 7, d = i & 127;
        sm[OFF_QT + d*16 + qq] = qb[i];
    }
    const float* kcb = gkcg + (size_t)b * Mn * Dn;
    const float* vcb = gvcg + (size_t)b * Mn * Dn;
    for (int i = tid; i < Mn*Dn; i += NT) {
        int j = i >> 7, d = i & 127;
        sm[OFF_KCG + j*CGP + d] = kcb[i];
        sm[OFF_VCG + j*CGP + d] = vcb[i];
    }
    __syncthreads();

    // ---- cg scores (16x8) ----
    if (tid < Qn*Mn) {
        int qq = tid >> 3, j = tid & 7;
        float acc = 0.f;
        #pragma unroll 8
        for (int d = 0; d < Dn; ++d)
            acc = fmaf(sm[OFF_QT + d*16 + qq], sm[OFF_KCG + j*CGP + d], acc);
        sm[OFF_PCG + qq*Mn + j] = acc * scale;
    }
    __syncthreads();
    // ---- cg softmax (rows of 8) ----
    if (tid < Qn) {
        float m = -1e30f;
        #pragma unroll
        for (int j = 0; j < Mn; ++j) m = fmaxf(m, sm[OFF_PCG + tid*Mn + j]);
        float ss = 0.f;
        #pragma unroll
        for (int j = 0; j < Mn; ++j) {
            float e = __expf(sm[OFF_PCG + tid*Mn + j] - m);
            sm[OFF_PCG + tid*Mn + j] = e; ss += e;
        }
        float inv = 1.f / ss;
        #pragma unroll
        for (int j = 0; j < Mn; ++j) sm[OFF_PCG + tid*Mn + j] *= inv;
    }
    __syncthreads();
    if (tid < Mn) {
        float a = 0.f;
        #pragma unroll
        for (int qq = 0; qq < Qn; ++qq) a += sm[OFF_PCG + qq*Mn + tid];
        sm[OFF_WCG + tid] = a;
    }
    // ---- cg out / kbar (packed) ----
    {
        int qq = tid >> 4, dblk = tid & 15;
        ull o2[4], kb2[4];
        #pragma unroll
        for (int i = 0; i < 4; ++i) { o2[i] = 0ull; kb2[i] = 0ull; }
        #pragma unroll
        for (int j = 0; j < Mn; ++j) {
            ull pc2 = dup2(sm[OFF_PCG + qq*Mn + j]);
            ulonglong2 vA = *(const ulonglong2*)&sm[OFF_VCG + j*CGP + dblk*8];
            ulonglong2 vB = *(const ulonglong2*)&sm[OFF_VCG + j*CGP + dblk*8 + 4];
            ulonglong2 kA = *(const ulonglong2*)&sm[OFF_KCG + j*CGP + dblk*8];
            ulonglong2 kB = *(const ulonglong2*)&sm[OFF_KCG + j*CGP + dblk*8 + 4];
            o2[0]  = fma2(pc2, vA.x, o2[0]);  o2[1]  = fma2(pc2, vA.y, o2[1]);
            o2[2]  = fma2(pc2, vB.x, o2[2]);  o2[3]  = fma2(pc2, vB.y, o2[3]);
            kb2[0] = fma2(pc2, kA.x, kb2[0]); kb2[1] = fma2(pc2, kA.y, kb2[1]);
            kb2[2] = fma2(pc2, kB.x, kb2[2]); kb2[3] = fma2(pc2, kB.y, kb2[3]);
        }
        *(ulonglong2*)&sm[OFF_OCG  + qq*Dn + dblk*8]     = make_ulonglong2(o2[0], o2[1]);
        *(ulonglong2*)&sm[OFF_OCG  + qq*Dn + dblk*8 + 4] = make_ulonglong2(o2[2], o2[3]);
        *(ulonglong2*)&sm[OFF_KBCG + qq*Dn + dblk*8]     = make_ulonglong2(kb2[0], kb2[1]);
        *(ulonglong2*)&sm[OFF_KBCG + qq*Dn + dblk*8 + 4] = make_ulonglong2(kb2[2], kb2[3]);
    }

    // ---- dense scores: p[q][s] = scale * q·k_s (packed) ----
    const float* kbase = gk + (size_t)b * Sn * Dn;
    const float* vbase = gv + (size_t)b * Sn * Dn;
    const int qg = tid >> 6;        // 4 groups of 4 queries
    const int sl = tid & 63;        // s within tile
    for (int t = 0; t < NTILES; ++t) {
        __syncthreads();
        const float4* kg4 = (const float4*)(kbase + (size_t)t * TILE * Dn);
        #pragma unroll
        for (int it = 0; it < 8; ++it) {
            int fidx = tid + it*NT;               // [0,2048)
            int row = fidx >> 5, c4 = fidx & 31;
            float4 val = kg4[fidx];
            float* dst = &sm[OFF_KTS + row*129 + c4*4];
            dst[0]=val.x; dst[1]=val.y; dst[2]=val.z; dst[3]=val.w;
        }
        __syncthreads();
        ull a01 = 0ull, a23 = 0ull;
        #pragma unroll 8
        for (int d = 0; d < Dn; ++d) {
            ull kv2 = dup2(sm[OFF_KTS + sl*129 + d]);
            ulonglong2 q2 = *(const ulonglong2*)&sm[OFF_QT + d*16 + qg*4];
            a01 = fma2(q2.x, kv2, a01);
            a23 = fma2(q2.y, kv2, a23);
        }
        float2 f01 = unpack2(a01), f23 = unpack2(a23);
        int scol = t*TILE + sl;
        sm[OFF_P + (qg*4+0)*PPITCH + scol] = f01.x*scale;
        sm[OFF_P + (qg*4+1)*PPITCH + scol] = f01.y*scale;
        sm[OFF_P + (qg*4+2)*PPITCH + scol] = f23.x*scale;
        sm[OFF_P + (qg*4+3)*PPITCH + scol] = f23.y*scale;
    }
    __syncthreads();

    // ---- softmax rows (warp handles rows wid and wid+8) ----
    const int wid = tid >> 5, lane = tid & 31;
    #pragma unroll
    for (int r = 0; r < 2; ++r) {
        int qq = wid + r*8;
        float* row = &sm[OFF_P + qq*PPITCH];
        float m = -1e30f;
        #pragma unroll
        for (int i = 0; i < 16; ++i) m = fmaxf(m, row[lane + 32*i]);
        #pragma unroll
        for (int o = 16; o > 0; o >>= 1) m = fmaxf(m, __shfl_xor_sync(0xffffffffu, m, o));
        float ss = 0.f;
        float ev[16];
        #pragma unroll
        for (int i = 0; i < 16; ++i) { ev[i] = __expf(row[lane+32*i] - m); ss += ev[i]; }
        #pragma unroll
        for (int o = 16; o > 0; o >>= 1) ss += __shfl_xor_sync(0xffffffffu, ss, o);
        float inv = 1.f / ss;
        #pragma unroll
        for (int i = 0; i < 16; ++i) row[lane+32*i] = ev[i]*inv;
    }
    __syncthreads();
    // ---- w[s] = column sums ----
    for (int s = tid; s < Sn; s += NT) {
        float a = 0.f;
        #pragma unroll
        for (int qq = 0; qq < Qn; ++qq) a += sm[OFF_P + qq*PPITCH + s];
        sm[OFF_W + s] = a;
    }

    // ---- fused main pass: J1 += w_j * v_j k_j^T ; out += pV ; kbar += pK ----
    const int ty = tid >> 4, tx = tid & 15;   // J tile: rows ty*8.., cols tx*8..
    ull acc2[8][4];
    #pragma unroll
    for (int i = 0; i < 8; ++i)
        #pragma unroll
        for (int e = 0; e < 4; ++e) acc2[i][e] = 0ull;
    ull ao2[4], ak2[4];
    #pragma unroll
    for (int i2 = 0; i2 < 4; ++i2) { ao2[i2] = 0ull; ak2[i2] = 0ull; }

    for (int t = 0; t < NTILES; ++t) {
        __syncthreads();
        const float4* kg4 = (const float4*)(kbase + (size_t)t * TILE * Dn);
        const float4* vg4 = (const float4*)(vbase + (size_t)t * TILE * Dn);
        #pragma unroll
        for (int it = 0; it < 8; ++it) {
            int fidx = tid + it*NT;
            ((float4*)&sm[OFF_KT])[fidx] = kg4[fidx];
            ((float4*)&sm[OFF_VT])[fidx] = vg4[fidx];
        }
        __syncthreads();
        #pragma unroll 2
        for (int j = 0; j < TILE; ++j) {
            float wj = sm[OFF_W + t*TILE + j];
            float4 va  = *(const float4*)&sm[OFF_VT + j*Dn + ty*8];
            float4 vb2 = *(const float4*)&sm[OFF_VT + j*Dn + ty*8 + 4];
            ull vd[8];
            vd[0]=dup2(va.x*wj);  vd[1]=dup2(va.y*wj);
            vd[2]=dup2(va.z*wj);  vd[3]=dup2(va.w*wj);
            vd[4]=dup2(vb2.x*wj); vd[5]=dup2(vb2.y*wj);
            vd[6]=dup2(vb2.z*wj); vd[7]=dup2(vb2.w*wj);
            ulonglong2 kA = *(const ulonglong2*)&sm[OFF_KT + j*Dn + tx*8];
            ulonglong2 kB = *(const ulonglong2*)&sm[OFF_KT + j*Dn + tx*8 + 4];
            ull kr2[4] = {kA.x, kA.y, kB.x, kB.y};
            #pragma unroll
            for (int i = 0; i < 8; ++i)
                #pragma unroll
                for (int e = 0; e < 4; ++e)
                    acc2[i][e] = fma2(vd[i], kr2[e], acc2[i][e]);
            // out / kbar (mapping: q-group qg, d-pair sl)
            ull vvp = *(const ull*)&sm[OFF_VT + j*Dn + sl*2];
            ull kkp = *(const ull*)&sm[OFF_KT + j*Dn + sl*2];
            #pragma unroll
            for (int i2 = 0; i2 < 4; ++i2) {
                ull pc2 = dup2(sm[OFF_P + (qg*4+i2)*PPITCH + t*TILE + j]);
                ao2[i2] = fma2(pc2, vvp, ao2[i2]);
                ak2[i2] = fma2(pc2, kkp, ak2[i2]);
            }
        }
    }
    // store out/kbar to smem
    #pragma unroll
    for (int i2 = 0; i2 < 4; ++i2) {
        *(ull*)&sm[OFF_OUT  + (qg*4+i2)*Dn + sl*2] = ao2[i2];
        *(ull*)&sm[OFF_KBAR + (qg*4+i2)*Dn + sl*2] = ak2[i2];
    }
    __syncthreads();

    // ---- dense J2: acc -= out_q (x) kbar_q (packed) ----
    #pragma unroll
    for (int qq = 0; qq < Qn; ++qq) {
        float4 oa = *(const float4*)&sm[OFF_OUT  + qq*Dn + ty*8];
        float4 ob = *(const float4*)&sm[OFF_OUT  + qq*Dn + ty*8 + 4];
        ulonglong2 k1 = *(const ulonglong2*)&sm[OFF_KBAR + qq*Dn + tx*8];
        ulonglong2 k2 = *(const ulonglong2*)&sm[OFF_KBAR + qq*Dn + tx*8 + 4];
        ull kb2[4] = {k1.x, k1.y, k2.x, k2.y};
        ull ovd[8];
        ovd[0]=dup2(-oa.x); ovd[1]=dup2(-oa.y); ovd[2]=dup2(-oa.z); ovd[3]=dup2(-oa.w);
        ovd[4]=dup2(-ob.x); ovd[5]=dup2(-ob.y); ovd[6]=dup2(-ob.z); ovd[7]=dup2(-ob.w);
        #pragma unroll
        for (int i = 0; i < 8; ++i)
            #pragma unroll
            for (int e = 0; e < 4; ++e)
                acc2[i][e] = fma2(ovd[i], kb2[e], acc2[i][e]);
    }

    // ---- cg jacobian (same thread tile, packed) ----
    ull jc2[8][4];
    #pragma unroll
    for (int i = 0; i < 8; ++i)
        #pragma unroll
        for (int e = 0; e < 4; ++e) jc2[i][e] = 0ull;
    #pragma unroll
    for (int j = 0; j < Mn; ++j) {
        float wj = sm[OFF_WCG + j];
        float4 va = *(const float4*)&sm[OFF_VCG + j*CGP + ty*8];
        float4 vb = *(const float4*)&sm[OFF_VCG + j*CGP + ty*8 + 4];
        ulonglong2 kA = *(const ulonglong2*)&sm[OFF_KCG + j*CGP + tx*8];
        ulonglong2 kB = *(const ulonglong2*)&sm[OFF_KCG + j*CGP + tx*8 + 4];
        ull kr2[4] = {kA.x, kA.y, kB.x, kB.y};
        ull vd[8];
        vd[0]=dup2(va.x*wj); vd[1]=dup2(va.y*wj); vd[2]=dup2(va.z*wj); vd[3]=dup2(va.w*wj);
        vd[4]=dup2(vb.x*wj); vd[5]=dup2(vb.y*wj); vd[6]=dup2(vb.z*wj); vd[7]=dup2(vb.w*wj);
        #pragma unroll
        for (int i = 0; i < 8; ++i)
            #pragma unroll
            for (int e = 0; e < 4; ++e)
                jc2[i][e] = fma2(vd[i], kr2[e], jc2[i][e]);
    }
    #pragma unroll
    for (int qq = 0; qq < Qn; ++qq) {
        float4 oa = *(const float4*)&sm[OFF_OCG + qq*Dn + ty*8];
        float4 ob = *(const float4*)&sm[OFF_OCG + qq*Dn + ty*8 + 4];
        ulonglong2 k1 = *(const ulonglong2*)&sm[OFF_KBCG + qq*Dn + tx*8];
        ulonglong2 k2 = *(const ulonglong2*)&sm[OFF_KBCG + qq*Dn + tx*8 + 4];
        ull kb2[4] = {k1.x, k1.y, k2.x, k2.y};
        ull ovd[8];
        ovd[0]=dup2(-oa.x); ovd[1]=dup2(-oa.y); ovd[2]=dup2(-oa.z); ovd[3]=dup2(-oa.w);
        ovd[4]=dup2(-ob.x); ovd[5]=dup2(-ob.y); ovd[6]=dup2(-ob.z); ovd[7]=dup2(-ob.w);
        #pragma unroll
        for (int i = 0; i < 8; ++i)
            #pragma unroll
            for (int e = 0; e < 4; ++e)
                jc2[i][e] = fma2(ovd[i], kb2[e], jc2[i][e]);
    }

    // ---- clip + cosine partials + consistency ----
    float dd = 0.f, cc = 0.f, dc = 0.f;
    #pragma unroll
    for (int i = 0; i < 8; ++i)
        #pragma unroll
        for (int e = 0; e < 4; ++e) {
            float2 ad = unpack2(acc2[i][e]);
            float2 jv = unpack2(jc2[i][e]);
            float jd0 = clip50(ad.x * scale), jc0 = clip50(jv.x * scale);
            float jd1 = clip50(ad.y * scale), jc1 = clip50(jv.y * scale);
            dd = fmaf(jd0, jd0, dd); dd = fmaf(jd1, jd1, dd);
            cc = fmaf(jc0, jc0, cc); cc = fmaf(jc1, jc1, cc);
            dc = fmaf(jd0, jc0, dc); dc = fmaf(jd1, jc1, dc);
        }
    float cons = 0.f;
    #pragma unroll
    for (int i = 0; i < 8; ++i) {
        float dif = sm[OFF_OUT + tid*8 + i] - sm[OFF_OCG + tid*8 + i];
        cons = fmaf(dif, dif, cons);
    }

    // ---- block reduce ----
    #pragma unroll
    for (int o = 16; o > 0; o >>= 1) {
        dd   += __shfl_xor_sync(0xffffffffu, dd,   o);
        cc   += __shfl_xor_sync(0xffffffffu, cc,   o);
        dc   += __shfl_xor_sync(0xffffffffu, dc,   o);
        cons += __shfl_xor_sync(0xffffffffu, cons, o);
    }
    if (lane == 0) {
        sm[OFF_RED + wid*4 + 0] = dd;
        sm[OFF_RED + wid*4 + 1] = cc;
        sm[OFF_RED + wid*4 + 2] = dc;
        sm[OFF_RED + wid*4 + 3] = cons;
    }
    __syncthreads();
    if (tid == 0) {
        float DD=0.f, CC=0.f, DC=0.f, CO=0.f;
        #pragma unroll
        for (int w8 = 0; w8 < 8; ++w8) {
            DD += sm[OFF_RED + w8*4 + 0];
            CC += sm[OFF_RED + w8*4 + 1];
            DC += sm[OFF_RED + w8*4 + 2];
            CO += sm[OFF_RED + w8*4 + 3];
        }
        float cosv = DC / (sqrtf(DD) * sqrtf(CC) + 1e-8f);
        g_losses[b] = (1.0f - cosv) + CO * (1.0f / (float)(Qn * Dn));
    }
}

__global__ void fml_reduce(float* out) {
    int lane = threadIdx.x;           // 32 threads
    float a = 0.f;
    #pragma unroll
    for (int i = 0; i < 8; ++i) a += g_losses[lane*8 + i];
    #pragma unroll
    for (int o = 16; o > 0; o >>= 1) a += __shfl_xor_sync(0xffffffffu, a, o);
    if (lane == 0) out[0] = a * (1.0f / (float)Bn);
}

extern "C" void kernel_launch(void* const* d_in, const int* in_sizes, int n_in,
                              void* d_out, int out_size)
{
    const float* q   = (const float*)d_in[0];
    const float* k   = (const float*)d_in[1];
    const float* v   = (const float*)d_in[2];
    const float* kcg = (const float*)d_in[3];
    const float* vcg = (const float*)d_in[4];

    cudaFuncSetAttribute(fml_kernel, cudaFuncAttributeMaxDynamicSharedMemorySize,
                         SMEM_FLOATS * (int)sizeof(float));
    fml_kernel<<<Bn, NT, SMEM_FLOATS * sizeof(float)>>>(q, k, v, kcg, vcg);
    fml_reduce<<<1, 32>>>((float*)d_out);
}